// round 1
// baseline (speedup 1.0000x reference)
#include <cuda_runtime.h>
#include <cuda_bf16.h>

// Problem constants
#define BB 64
#define TT 2048
#define DD 512
#define UU 512

// Scratch (no cudaMalloc allowed)
__device__ float g_hb[BB * UU];        // h_proj + W1_b  (per batch)
__device__ float g_logits[BB * TT];    // pre-softmax logits

typedef unsigned long long ull;

__device__ __forceinline__ void fma2(ull& d, ull a, ull b) {
    asm("fma.rn.f32x2 %0, %1, %2, %0;" : "+l"(d) : "l"(a), "l"(b));
}
__device__ __forceinline__ ull pack2(float x, float y) {
    ull d; asm("mov.b64 %0, {%1, %2};" : "=l"(d) : "f"(x), "f"(y)); return d;
}
__device__ __forceinline__ void unpack2(ull v, float& x, float& y) {
    asm("mov.b64 {%0, %1}, %2;" : "=f"(x), "=f"(y) : "l"(v));
}
__device__ __forceinline__ float tanh_fast(float x) {
    float y; asm("tanh.approx.f32 %0, %1;" : "=f"(y) : "f"(x)); return y;
}

// ---------------------------------------------------------------------------
// Kernel 1: g_hb[b,u] = hidden[b,:] @ W2[:,u] + W2_b[u] + W1_b[u]
// ---------------------------------------------------------------------------
__global__ __launch_bounds__(512) void k_hproj(
    const float* __restrict__ hidden, const float* __restrict__ W2,
    const float* __restrict__ W2b, const float* __restrict__ W1b)
{
    int b = blockIdx.x;
    int u = threadIdx.x;
    __shared__ float h[DD];
    h[u] = hidden[b * DD + u];
    __syncthreads();
    float a0 = 0.f, a1 = 0.f, a2 = 0.f, a3 = 0.f;
    #pragma unroll 4
    for (int k = 0; k < DD; k += 4) {
        a0 = fmaf(h[k + 0], W2[(k + 0) * UU + u], a0);
        a1 = fmaf(h[k + 1], W2[(k + 1) * UU + u], a1);
        a2 = fmaf(h[k + 2], W2[(k + 2) * UU + u], a2);
        a3 = fmaf(h[k + 3], W2[(k + 3) * UU + u], a3);
    }
    g_hb[b * UU + u] = ((a0 + a1) + (a2 + a3)) + W2b[u] + W1b[u];
}

// ---------------------------------------------------------------------------
// Kernel 2: fused  logits[m] = sum_u tanh( (F@W1)[m,u] + g_hb[b,u] ) * v[u]
// BM=32 rows per block (stays within one b), full U=512, BK=16, 256 threads.
// f32x2 packed accumulators: 8 rows x 8 cols (4 pairs) per thread.
// ---------------------------------------------------------------------------
#define BM 32
#define BK 16

__global__ __launch_bounds__(256) void k_logits(
    const float* __restrict__ F, const float* __restrict__ W1,
    const float* __restrict__ V)
{
    __shared__ float Ws[BK][UU];       // 32 KB
    __shared__ float Fs[BK][BM];       // 2 KB
    __shared__ float gs[UU];           // 2 KB
    __shared__ float vs[UU];           // 2 KB
    __shared__ float red[BM][65];      // 8.1 KB (pad 65 -> conflict-free column read)

    const int tid = threadIdx.x;
    const int m0  = blockIdx.x * BM;
    const int b   = m0 >> 11;          // m0 / TT
    const int tx  = tid & 63;          // col group: 64 groups of 8 cols
    const int ty  = tid >> 6;          // row group: 4 groups of 8 rows

    for (int i = tid; i < UU; i += 256) {
        gs[i] = g_hb[b * UU + i];
        vs[i] = V[i];
    }

    ull acc[8][4];
    #pragma unroll
    for (int r = 0; r < 8; r++)
        #pragma unroll
        for (int j = 0; j < 4; j++) acc[r][j] = 0ull;

    for (int k0 = 0; k0 < DD; k0 += BK) {
        __syncthreads();
        // Load W1 tile [BK][512]: 2048 float4s, 8 per thread, coalesced
        #pragma unroll
        for (int i = 0; i < 8; i++) {
            int lin = tid + i * 256;
            int kk  = lin >> 7;
            int u4  = (lin & 127) << 2;
            *(float4*)&Ws[kk][u4] = *(const float4*)&W1[(size_t)(k0 + kk) * UU + u4];
        }
        // Load F tile [BM][BK] transposed into Fs[k][m]
        if (tid < 128) {
            int m   = tid >> 2;
            int kk4 = (tid & 3) << 2;
            float4 f = *(const float4*)&F[(size_t)(m0 + m) * DD + k0 + kk4];
            Fs[kk4 + 0][m] = f.x; Fs[kk4 + 1][m] = f.y;
            Fs[kk4 + 2][m] = f.z; Fs[kk4 + 3][m] = f.w;
        }
        __syncthreads();

        #pragma unroll
        for (int kk = 0; kk < BK; kk++) {
            float4 fa = *(float4*)&Fs[kk][ty * 8];
            float4 fb = *(float4*)&Fs[kk][ty * 8 + 4];
            float4 wa = *(float4*)&Ws[kk][tx * 8];
            float4 wb = *(float4*)&Ws[kk][tx * 8 + 4];
            ull w2[4];
            w2[0] = pack2(wa.x, wa.y); w2[1] = pack2(wa.z, wa.w);
            w2[2] = pack2(wb.x, wb.y); w2[3] = pack2(wb.z, wb.w);
            float fr[8] = {fa.x, fa.y, fa.z, fa.w, fb.x, fb.y, fb.z, fb.w};
            #pragma unroll
            for (int r = 0; r < 8; r++) {
                ull f2 = pack2(fr[r], fr[r]);
                fma2(acc[r][0], f2, w2[0]);
                fma2(acc[r][1], f2, w2[1]);
                fma2(acc[r][2], f2, w2[2]);
                fma2(acc[r][3], f2, w2[3]);
            }
        }
    }

    // Epilogue: tanh(x + g) * v, partial per (row, col-group)
    #pragma unroll
    for (int r = 0; r < 8; r++) {
        float p = 0.f;
        #pragma unroll
        for (int j = 0; j < 4; j++) {
            float x0, x1;
            unpack2(acc[r][j], x0, x1);
            int u = tx * 8 + j * 2;
            p += tanh_fast(x0 + gs[u])     * vs[u];
            p += tanh_fast(x1 + gs[u + 1]) * vs[u + 1];
        }
        red[ty * 8 + r][tx] = p;
    }
    __syncthreads();
    if (tid < BM) {
        float s = 0.f;
        #pragma unroll 8
        for (int i = 0; i < 64; i++) s += red[tid][i];
        g_logits[m0 + tid] = s;
    }
}

// ---------------------------------------------------------------------------
// Kernel 3: softmax over T per batch, write attention weights
// ---------------------------------------------------------------------------
__global__ __launch_bounds__(256) void k_softmax(float* __restrict__ out_w)
{
    int b = blockIdx.x;
    int tid = threadIdx.x;
    const float* lg = &g_logits[b * TT];
    __shared__ float smax[8], ssum[8];

    float v[8];
    float mx = -1e30f;
    #pragma unroll
    for (int i = 0; i < 8; i++) {
        v[i] = lg[tid + i * 256];
        mx = fmaxf(mx, v[i]);
    }
    #pragma unroll
    for (int o = 16; o > 0; o >>= 1) mx = fmaxf(mx, __shfl_xor_sync(~0u, mx, o));
    if ((tid & 31) == 0) smax[tid >> 5] = mx;
    __syncthreads();
    mx = smax[0];
    #pragma unroll
    for (int i = 1; i < 8; i++) mx = fmaxf(mx, smax[i]);

    float s = 0.f;
    #pragma unroll
    for (int i = 0; i < 8; i++) {
        v[i] = expf(v[i] - mx);
        s += v[i];
    }
    #pragma unroll
    for (int o = 16; o > 0; o >>= 1) s += __shfl_xor_sync(~0u, s, o);
    if ((tid & 31) == 0) ssum[tid >> 5] = s;
    __syncthreads();
    s = ssum[0];
    #pragma unroll
    for (int i = 1; i < 8; i++) s += ssum[i];
    float inv = 1.f / s;

    #pragma unroll
    for (int i = 0; i < 8; i++)
        out_w[b * TT + tid + i * 256] = v[i] * inv;
}

// ---------------------------------------------------------------------------
// Kernel 4: context[b,d] = sum_t w[b,t] * F[b,t,d]
// grid: (b, d-chunk of 128); 128 threads, one d each; t chunked through smem
// ---------------------------------------------------------------------------
__global__ __launch_bounds__(128) void k_context(
    const float* __restrict__ F, const float* __restrict__ w,
    float* __restrict__ out_c)
{
    int b  = blockIdx.x >> 2;
    int d0 = (blockIdx.x & 3) << 7;
    int tid = threadIdx.x;
    __shared__ float ws[128];
    const float* Fb = F + (size_t)b * TT * DD + d0;
    const float* wb = w + b * TT;

    float a0 = 0.f, a1 = 0.f, a2 = 0.f, a3 = 0.f;
    for (int t0 = 0; t0 < TT; t0 += 128) {
        __syncthreads();
        ws[tid] = wb[t0 + tid];
        __syncthreads();
        #pragma unroll 4
        for (int i = 0; i < 128; i += 4) {
            a0 = fmaf(ws[i + 0], Fb[(size_t)(t0 + i + 0) * DD + tid], a0);
            a1 = fmaf(ws[i + 1], Fb[(size_t)(t0 + i + 1) * DD + tid], a1);
            a2 = fmaf(ws[i + 2], Fb[(size_t)(t0 + i + 2) * DD + tid], a2);
            a3 = fmaf(ws[i + 3], Fb[(size_t)(t0 + i + 3) * DD + tid], a3);
        }
    }
    out_c[b * DD + d0 + tid] = (a0 + a1) + (a2 + a3);
}

// ---------------------------------------------------------------------------
extern "C" void kernel_launch(void* const* d_in, const int* in_sizes, int n_in,
                              void* d_out, int out_size)
{
    const float* features = (const float*)d_in[0];
    const float* hidden   = (const float*)d_in[1];
    const float* W1_w     = (const float*)d_in[2];
    const float* W1_b     = (const float*)d_in[3];
    const float* W2_w     = (const float*)d_in[4];
    const float* W2_b     = (const float*)d_in[5];
    const float* V_w      = (const float*)d_in[6];
    // V_b (d_in[7]) cancels in softmax; unused.

    float* out   = (float*)d_out;
    float* out_c = out;                  // [B, D]   = 32768 floats
    float* out_w = out + BB * DD;        // [B, T, 1] = 131072 floats

    k_hproj  <<<BB, 512>>>(hidden, W2_w, W2_b, W1_b);
    k_logits <<<(BB * TT) / BM, 256>>>(features, W1_w, V_w);
    k_softmax<<<BB, 256>>>(out_w);
    k_context<<<BB * 4, 128>>>(features, out_w, out_c);
}

// round 4
// speedup vs baseline: 1.9082x; 1.9082x over previous
#include <cuda_runtime.h>
#include <cuda_bf16.h>
#include <cstdint>

#define BB 64
#define TT 2048
#define DD 512
#define UU 512

// ---------------- device scratch (no cudaMalloc allowed) ----------------
__device__ float g_hb[BB * UU];                 // h_proj + W1_b
__device__ float g_lpart[4][BB * TT];           // logits partials per u-slice
__device__ float g_part[BB][32][2][DD];         // context partials
__device__ __nv_bfloat16 g_W1h[UU * DD];        // W1^T hi  [u][k]
__device__ __nv_bfloat16 g_W1l[UU * DD];        // W1^T lo  [u][k]

// ---------------- helpers ----------------
__device__ __forceinline__ uint32_t smem_u32(const void* p) {
    uint32_t a;
    asm("{ .reg .u64 t; cvta.to.shared.u64 t, %1; cvt.u32.u64 %0, t; }" : "=r"(a) : "l"(p));
    return a;
}
__device__ __forceinline__ float tanh_fast(float x) {
    float y; asm("tanh.approx.f32 %0, %1;" : "=f"(y) : "f"(x)); return y;
}
__device__ __forceinline__ void cp16(uint32_t dst, const void* src) {
    asm volatile("cp.async.cg.shared.global [%0], [%1], 16;" :: "r"(dst), "l"(src) : "memory");
}
__device__ __forceinline__ void ldsm4(uint32_t* r, uint32_t addr) {
    asm volatile("ldmatrix.sync.aligned.m8n8.x4.shared.b16 {%0,%1,%2,%3}, [%4];"
                 : "=r"(r[0]), "=r"(r[1]), "=r"(r[2]), "=r"(r[3]) : "r"(addr));
}
__device__ __forceinline__ void mma_bf16(float* c, const uint32_t* a, const uint32_t* b) {
    asm volatile("mma.sync.aligned.m16n8k16.row.col.f32.bf16.bf16.f32 "
                 "{%0,%1,%2,%3}, {%4,%5,%6,%7}, {%8,%9}, {%0,%1,%2,%3};"
                 : "+f"(c[0]), "+f"(c[1]), "+f"(c[2]), "+f"(c[3])
                 : "r"(a[0]), "r"(a[1]), "r"(a[2]), "r"(a[3]), "r"(b[0]), "r"(b[1]));
}

// ---------------------------------------------------------------------------
// k_prepw: W1 [k][u] -> W1^T hi/lo bf16 [u][k]
// ---------------------------------------------------------------------------
__global__ __launch_bounds__(512) void k_prepw(const float* __restrict__ W1) {
    int u = blockIdx.x, k = threadIdx.x;
    float x = W1[(size_t)k * UU + u];
    __nv_bfloat16 h = __float2bfloat16_rn(x);
    __nv_bfloat16 l = __float2bfloat16_rn(x - __bfloat162float(h));
    g_W1h[(size_t)u * DD + k] = h;
    g_W1l[(size_t)u * DD + k] = l;
}

// ---------------------------------------------------------------------------
// k_hproj: g_hb[b,u] = hidden[b,:] @ W2[:,u] + W2_b[u] + W1_b[u]
// ---------------------------------------------------------------------------
__global__ __launch_bounds__(512) void k_hproj(
    const float* __restrict__ hidden, const float* __restrict__ W2,
    const float* __restrict__ W2b, const float* __restrict__ W1b)
{
    int b = blockIdx.x, u = threadIdx.x;
    __shared__ float h[DD];
    h[u] = hidden[b * DD + u];
    __syncthreads();
    float a0 = 0.f, a1 = 0.f, a2 = 0.f, a3 = 0.f;
    #pragma unroll 4
    for (int k = 0; k < DD; k += 4) {
        a0 = fmaf(h[k + 0], W2[(k + 0) * UU + u], a0);
        a1 = fmaf(h[k + 1], W2[(k + 1) * UU + u], a1);
        a2 = fmaf(h[k + 2], W2[(k + 2) * UU + u], a2);
        a3 = fmaf(h[k + 3], W2[(k + 3) * UU + u], a3);
    }
    g_hb[b * UU + u] = ((a0 + a1) + (a2 + a3)) + W2b[u] + W1b[u];
}

// ---------------------------------------------------------------------------
// k_logits: mma.sync bf16 split GEMM + fused tanh/v epilogue (partial over u)
// ---------------------------------------------------------------------------
#define OFF_AH(b) ((b) * 40960 + 0)
#define OFF_AL(b) ((b) * 40960 + 10240)
#define OFF_BH(b) ((b) * 40960 + 20480)
#define OFF_BL(b) ((b) * 40960 + 30720)
#define OFF_GS 81920
#define OFF_VS 82432
#define OFF_RED 82944
#define SMEM_BYTES 87552

__global__ __launch_bounds__(256, 1)
void k_logits(const float* __restrict__ F, const float* __restrict__ V)
{
    extern __shared__ __align__(128) uint8_t smem[];
    const uint32_t sb = smem_u32(smem);
    const int tid = threadIdx.x;
    const int lane = tid & 31, wid = tid >> 5;
    const int warp_m = wid & 3, warp_n = wid >> 2;
    const int m0 = blockIdx.x * 128;
    const int b  = m0 >> 11;
    const int us = blockIdx.y;

    float* gs  = (float*)(smem + OFF_GS);
    float* vsm = (float*)(smem + OFF_VS);
    if (tid < 128) {
        gs[tid]  = g_hb[b * UU + us * 128 + tid];
        vsm[tid] = V[us * 128 + tid];
    }

    const int arow = tid >> 1, ah = tid & 1;

    auto cpB = [&](int kt, int buf) {
        const __nv_bfloat16* sh = g_W1h + (size_t)(us * 128 + arow) * DD + kt * 32 + ah * 16;
        const __nv_bfloat16* sl = g_W1l + (size_t)(us * 128 + arow) * DD + kt * 32 + ah * 16;
        uint32_t d = (uint32_t)(arow * 80 + ah * 32);
        cp16(sb + OFF_BH(buf) + d,      sh);
        cp16(sb + OFF_BH(buf) + d + 16, sh + 8);
        cp16(sb + OFF_BL(buf) + d,      sl);
        cp16(sb + OFF_BL(buf) + d + 16, sl + 8);
    };
    auto ldA = [&](int kt, float4* fr) {
        const float4* p = (const float4*)(F + (size_t)(m0 + arow) * DD + kt * 32 + ah * 16);
        fr[0] = p[0]; fr[1] = p[1]; fr[2] = p[2]; fr[3] = p[3];
    };
    auto stA = [&](const float4* fr, int buf) {
        float x[16] = {fr[0].x, fr[0].y, fr[0].z, fr[0].w, fr[1].x, fr[1].y, fr[1].z, fr[1].w,
                       fr[2].x, fr[2].y, fr[2].z, fr[2].w, fr[3].x, fr[3].y, fr[3].z, fr[3].w};
        uint32_t hw[8], lw[8];
        #pragma unroll
        for (int i = 0; i < 8; i++) {
            float a = x[2 * i], c = x[2 * i + 1];
            __nv_bfloat16 hA = __float2bfloat16_rn(a), hC = __float2bfloat16_rn(c);
            __nv_bfloat16 lA = __float2bfloat16_rn(a - __bfloat162float(hA));
            __nv_bfloat16 lC = __float2bfloat16_rn(c - __bfloat162float(hC));
            hw[i] = (uint32_t)__bfloat16_as_ushort(hA) | ((uint32_t)__bfloat16_as_ushort(hC) << 16);
            lw[i] = (uint32_t)__bfloat16_as_ushort(lA) | ((uint32_t)__bfloat16_as_ushort(lC) << 16);
        }
        uint32_t d = (uint32_t)(arow * 80 + ah * 32);
        *(uint4*)(smem + OFF_AH(buf) + d)      = make_uint4(hw[0], hw[1], hw[2], hw[3]);
        *(uint4*)(smem + OFF_AH(buf) + d + 16) = make_uint4(hw[4], hw[5], hw[6], hw[7]);
        *(uint4*)(smem + OFF_AL(buf) + d)      = make_uint4(lw[0], lw[1], lw[2], lw[3]);
        *(uint4*)(smem + OFF_AL(buf) + d + 16) = make_uint4(lw[4], lw[5], lw[6], lw[7]);
    };

    float acc[2][8][4];
    #pragma unroll
    for (int i = 0; i < 2; i++)
        #pragma unroll
        for (int j = 0; j < 8; j++)
            #pragma unroll
            for (int q = 0; q < 4; q++) acc[i][j][q] = 0.f;

    float4 fr[4];
    cpB(0, 0); asm volatile("cp.async.commit_group;" ::: "memory");
    cpB(1, 1); asm volatile("cp.async.commit_group;" ::: "memory");
    ldA(0, fr); stA(fr, 0);
    ldA(1, fr);
    asm volatile("cp.async.wait_group 1;" ::: "memory");
    __syncthreads();

    #pragma unroll 1
    for (int t = 0; t < 16; t++) {
        const int buf = t & 1;
        const uint32_t ahb = sb + OFF_AH(buf), alb = sb + OFF_AL(buf);
        const uint32_t bhb = sb + OFF_BH(buf), blb = sb + OFF_BL(buf);
        #pragma unroll
        for (int ks = 0; ks < 2; ks++) {
            const uint32_t kb = ks * 32;
            uint32_t Ah[2][4], Al[2][4], Bv[4][4], boff[4];
            #pragma unroll
            for (int mt = 0; mt < 2; mt++) {
                uint32_t ro = (uint32_t)(warp_m * 32 + mt * 16 + (lane & 15)) * 80 + kb + ((lane >> 4) << 4);
                ldsm4(Ah[mt], ahb + ro);
                ldsm4(Al[mt], alb + ro);
            }
            #pragma unroll
            for (int p = 0; p < 4; p++) {
                boff[p] = (uint32_t)(warp_n * 64 + p * 16 + ((lane >> 4) << 3) + (lane & 7)) * 80
                          + kb + (((lane >> 3) & 1) << 4);
                ldsm4(Bv[p], bhb + boff[p]);
            }
            #pragma unroll
            for (int mt = 0; mt < 2; mt++)
                #pragma unroll
                for (int p = 0; p < 4; p++) {
                    mma_bf16(acc[mt][2 * p],     Ah[mt], &Bv[p][0]);
                    mma_bf16(acc[mt][2 * p + 1], Ah[mt], &Bv[p][2]);
                    mma_bf16(acc[mt][2 * p],     Al[mt], &Bv[p][0]);
                    mma_bf16(acc[mt][2 * p + 1], Al[mt], &Bv[p][2]);
                }
            #pragma unroll
            for (int p = 0; p < 4; p++) ldsm4(Bv[p], blb + boff[p]);
            #pragma unroll
            for (int mt = 0; mt < 2; mt++)
                #pragma unroll
                for (int p = 0; p < 4; p++) {
                    mma_bf16(acc[mt][2 * p],     Ah[mt], &Bv[p][0]);
                    mma_bf16(acc[mt][2 * p + 1], Ah[mt], &Bv[p][2]);
                }
        }
        if (t == 15) break;
        __syncthreads();
        stA(fr, (t + 1) & 1);
        if (t + 2 < 16) {
            ldA(t + 2, fr);
            cpB(t + 2, buf);
            asm volatile("cp.async.commit_group;" ::: "memory");
            asm volatile("cp.async.wait_group 1;" ::: "memory");
        } else {
            asm volatile("cp.async.wait_group 0;" ::: "memory");
        }
        __syncthreads();
    }

    // epilogue: partial logits over this u-slice
    float* red = (float*)(smem + OFF_RED);
    #pragma unroll
    for (int mt = 0; mt < 2; mt++)
        #pragma unroll
        for (int hf = 0; hf < 2; hf++) {
            float p = 0.f;
            #pragma unroll
            for (int nt = 0; nt < 8; nt++) {
                int u = warp_n * 64 + nt * 8 + (lane & 3) * 2;
                p += tanh_fast(acc[mt][nt][hf * 2 + 0] + gs[u])     * vsm[u];
                p += tanh_fast(acc[mt][nt][hf * 2 + 1] + gs[u + 1]) * vsm[u + 1];
            }
            int ml = warp_m * 32 + mt * 16 + hf * 8 + (lane >> 2);
            red[ml * 9 + warp_n * 4 + (lane & 3)] = p;
        }
    __syncthreads();
    if (tid < 128) {
        float s = 0.f;
        #pragma unroll
        for (int i = 0; i < 8; i++) s += red[tid * 9 + i];
        g_lpart[us][m0 + tid] = s;
    }
}

// ---------------------------------------------------------------------------
// k_softmax: sum u-slice partials, softmax over T
// ---------------------------------------------------------------------------
__global__ __launch_bounds__(256) void k_softmax(float* __restrict__ out_w)
{
    int b = blockIdx.x, tid = threadIdx.x;
    __shared__ float smax[8], ssum[8];
    float v[8];
    float mx = -1e30f;
    #pragma unroll
    for (int i = 0; i < 8; i++) {
        int idx = b * TT + tid + i * 256;
        v[i] = g_lpart[0][idx] + g_lpart[1][idx] + g_lpart[2][idx] + g_lpart[3][idx];
        mx = fmaxf(mx, v[i]);
    }
    #pragma unroll
    for (int o = 16; o > 0; o >>= 1) mx = fmaxf(mx, __shfl_xor_sync(~0u, mx, o));
    if ((tid & 31) == 0) smax[tid >> 5] = mx;
    __syncthreads();
    mx = smax[0];
    #pragma unroll
    for (int i = 1; i < 8; i++) mx = fmaxf(mx, smax[i]);
    float s = 0.f;
    #pragma unroll
    for (int i = 0; i < 8; i++) { v[i] = expf(v[i] - mx); s += v[i]; }
    #pragma unroll
    for (int o = 16; o > 0; o >>= 1) s += __shfl_xor_sync(~0u, s, o);
    if ((tid & 31) == 0) ssum[tid >> 5] = s;
    __syncthreads();
    s = ssum[0];
    #pragma unroll
    for (int i = 1; i < 8; i++) s += ssum[i];
    float inv = 1.f / s;
    #pragma unroll
    for (int i = 0; i < 8; i++) out_w[b * TT + tid + i * 256] = v[i] * inv;
}

// ---------------------------------------------------------------------------
// k_ctx_part / k_ctx_red: context = sum_t w * F, two-stage deterministic
// ---------------------------------------------------------------------------
__global__ __launch_bounds__(256) void k_ctx_part(
    const float* __restrict__ F, const float* __restrict__ w)
{
    int tc = blockIdx.x, b = blockIdx.y, tid = threadIdx.x;
    __shared__ float ws[64];
    if (tid < 64) ws[tid] = w[b * TT + tc * 64 + tid];
    __syncthreads();
    int q = tid & 127, r2 = tid >> 7;
    const float4* F4 = (const float4*)(F + ((size_t)b * TT + (size_t)tc * 64) * DD) + q;
    float ax = 0.f, ay = 0.f, az = 0.f, aw = 0.f;
    #pragma unroll 8
    for (int i = 0; i < 32; i++) {
        int t = r2 + 2 * i;
        float wv = ws[t];
        float4 v = F4[(size_t)t * 128];
        ax = fmaf(wv, v.x, ax); ay = fmaf(wv, v.y, ay);
        az = fmaf(wv, v.z, az); aw = fmaf(wv, v.w, aw);
    }
    float4 o; o.x = ax; o.y = ay; o.z = az; o.w = aw;
    ((float4*)&g_part[b][tc][r2][0])[q] = o;
}

__global__ __launch_bounds__(512) void k_ctx_red(float* __restrict__ out_c)
{
    int b = blockIdx.x, d = threadIdx.x;
    float s = 0.f;
    const float* p = &g_part[b][0][0][0];
    #pragma unroll
    for (int i = 0; i < 64; i++) s += p[i * DD + d];
    out_c[b * DD + d] = s;
}

// ---------------------------------------------------------------------------
extern "C" void kernel_launch(void* const* d_in, const int* in_sizes, int n_in,
                              void* d_out, int out_size)
{
    const float* features = (const float*)d_in[0];
    const float* hidden   = (const float*)d_in[1];
    const float* W1_w     = (const float*)d_in[2];
    const float* W1_b     = (const float*)d_in[3];
    const float* W2_w     = (const float*)d_in[4];
    const float* W2_b     = (const float*)d_in[5];
    const float* V_w      = (const float*)d_in[6];
    // V_b cancels in softmax

    float* out   = (float*)d_out;
    float* out_c = out;               // [B, D]
    float* out_w = out + BB * DD;     // [B, T, 1]

    cudaFuncSetAttribute(k_logits, cudaFuncAttributeMaxDynamicSharedMemorySize, SMEM_BYTES);

    k_prepw  <<<512, 512>>>(W1_w);
    k_hproj  <<<BB, 512>>>(hidden, W2_w, W2_b, W1_b);
    k_logits <<<dim3(1024, 4), 256, SMEM_BYTES>>>(features, V_w);
    k_softmax<<<BB, 256>>>(out_w);
    k_ctx_part<<<dim3(32, BB), 256>>>(features, out_w);
    k_ctx_red<<<BB, 512>>>(out_c);
}

// round 6
// speedup vs baseline: 3.0583x; 1.6027x over previous
#include <cuda_runtime.h>
#include <cuda_fp16.h>
#include <cuda_bf16.h>
#include <cstdint>

#define BB 64
#define TT 2048
#define DD 512
#define UU 512

// ---------------- device scratch (no cudaMalloc allowed) ----------------
__device__ float g_hb[BB * UU];                 // h_proj + W1_b
__device__ float g_lpart[4][BB * TT];           // logits partials per u-slice
__device__ float g_part[BB][32][2][DD];         // context partials
__device__ __half g_W1f[UU * DD];               // W1^T fp16  [u][k]

// ---------------- helpers ----------------
__device__ __forceinline__ uint32_t smem_u32(const void* p) {
    uint32_t a;
    asm("{ .reg .u64 t; cvta.to.shared.u64 t, %1; cvt.u32.u64 %0, t; }" : "=r"(a) : "l"(p));
    return a;
}
__device__ __forceinline__ float tanh_fast(float x) {
    float y; asm("tanh.approx.f32 %0, %1;" : "=f"(y) : "f"(x)); return y;
}
__device__ __forceinline__ void cp16(uint32_t dst, const void* src) {
    asm volatile("cp.async.cg.shared.global [%0], [%1], 16;" :: "r"(dst), "l"(src) : "memory");
}
__device__ __forceinline__ void ldsm4(uint32_t* r, uint32_t addr) {
    asm volatile("ldmatrix.sync.aligned.m8n8.x4.shared.b16 {%0,%1,%2,%3}, [%4];"
                 : "=r"(r[0]), "=r"(r[1]), "=r"(r[2]), "=r"(r[3]) : "r"(addr));
}
__device__ __forceinline__ void mma_f16(float* c, const uint32_t* a, const uint32_t* b) {
    asm volatile("mma.sync.aligned.m16n8k16.row.col.f32.f16.f16.f32 "
                 "{%0,%1,%2,%3}, {%4,%5,%6,%7}, {%8,%9}, {%0,%1,%2,%3};"
                 : "+f"(c[0]), "+f"(c[1]), "+f"(c[2]), "+f"(c[3])
                 : "r"(a[0]), "r"(a[1]), "r"(a[2]), "r"(a[3]), "r"(b[0]), "r"(b[1]));
}

// ---------------------------------------------------------------------------
// k_prepw: W1 [k][u] -> W1^T fp16 [u][k]
// ---------------------------------------------------------------------------
__global__ __launch_bounds__(512) void k_prepw(const float* __restrict__ W1) {
    int u = blockIdx.x, k = threadIdx.x;
    g_W1f[(size_t)u * DD + k] = __float2half_rn(W1[(size_t)k * UU + u]);
}

// ---------------------------------------------------------------------------
// k_hproj: g_hb[b,u] = hidden[b,:] @ W2[:,u] + W2_b[u] + W1_b[u]
// ---------------------------------------------------------------------------
__global__ __launch_bounds__(512) void k_hproj(
    const float* __restrict__ hidden, const float* __restrict__ W2,
    const float* __restrict__ W2b, const float* __restrict__ W1b)
{
    int b = blockIdx.x, u = threadIdx.x;
    __shared__ float h[DD];
    h[u] = hidden[b * DD + u];
    __syncthreads();
    float a0 = 0.f, a1 = 0.f, a2 = 0.f, a3 = 0.f;
    #pragma unroll 4
    for (int k = 0; k < DD; k += 4) {
        a0 = fmaf(h[k + 0], W2[(k + 0) * UU + u], a0);
        a1 = fmaf(h[k + 1], W2[(k + 1) * UU + u], a1);
        a2 = fmaf(h[k + 2], W2[(k + 2) * UU + u], a2);
        a3 = fmaf(h[k + 3], W2[(k + 3) * UU + u], a3);
    }
    g_hb[b * UU + u] = ((a0 + a1) + (a2 + a3)) + W2b[u] + W1b[u];
}

// ---------------------------------------------------------------------------
// k_logits: mma.sync fp16 2-pass split GEMM + fused tanh/v epilogue
//   A = features split into fp16 hi+lo (exact to ~2^-22), B = W1 single fp16.
// ---------------------------------------------------------------------------
#define OFF_AH(b) ((b) * 30720 + 0)
#define OFF_AL(b) ((b) * 30720 + 10240)
#define OFF_B(b)  ((b) * 30720 + 20480)
#define OFF_GS 61440
#define OFF_VS 61952
#define OFF_RED 62464
#define SMEM_BYTES 67072

__global__ __launch_bounds__(256, 2)
void k_logits(const float* __restrict__ F, const float* __restrict__ V)
{
    extern __shared__ __align__(128) uint8_t smem[];
    const uint32_t sb = smem_u32(smem);
    const int tid = threadIdx.x;
    const int lane = tid & 31, wid = tid >> 5;
    const int warp_m = wid & 3, warp_n = wid >> 2;
    const int m0 = blockIdx.x * 128;
    const int b  = m0 >> 11;
    const int us = blockIdx.y;

    float* gs  = (float*)(smem + OFF_GS);
    float* vsm = (float*)(smem + OFF_VS);
    if (tid < 128) {
        gs[tid]  = g_hb[b * UU + us * 128 + tid];
        vsm[tid] = V[us * 128 + tid];
    }

    const int arow = tid >> 1, ah = tid & 1;

    auto cpB = [&](int kt, int buf) {
        const __half* s = g_W1f + (size_t)(us * 128 + arow) * DD + kt * 32 + ah * 16;
        uint32_t d = (uint32_t)(arow * 80 + ah * 32);
        cp16(sb + OFF_B(buf) + d,      s);
        cp16(sb + OFF_B(buf) + d + 16, s + 8);
    };
    auto ldA = [&](int kt, float4* fr) {
        const float4* p = (const float4*)(F + (size_t)(m0 + arow) * DD + kt * 32 + ah * 16);
        fr[0] = p[0]; fr[1] = p[1]; fr[2] = p[2]; fr[3] = p[3];
    };
    auto stA = [&](const float4* fr, int buf) {
        float x[16] = {fr[0].x, fr[0].y, fr[0].z, fr[0].w, fr[1].x, fr[1].y, fr[1].z, fr[1].w,
                       fr[2].x, fr[2].y, fr[2].z, fr[2].w, fr[3].x, fr[3].y, fr[3].z, fr[3].w};
        uint32_t hw[8], lw[8];
        #pragma unroll
        for (int i = 0; i < 8; i++) {
            float a = x[2 * i], c = x[2 * i + 1];
            __half hA = __float2half_rn(a), hC = __float2half_rn(c);
            __half lA = __float2half_rn(a - __half2float(hA));
            __half lC = __float2half_rn(c - __half2float(hC));
            hw[i] = (uint32_t)__half_as_ushort(hA) | ((uint32_t)__half_as_ushort(hC) << 16);
            lw[i] = (uint32_t)__half_as_ushort(lA) | ((uint32_t)__half_as_ushort(lC) << 16);
        }
        uint32_t d = (uint32_t)(arow * 80 + ah * 32);
        *(uint4*)(smem + OFF_AH(buf) + d)      = make_uint4(hw[0], hw[1], hw[2], hw[3]);
        *(uint4*)(smem + OFF_AH(buf) + d + 16) = make_uint4(hw[4], hw[5], hw[6], hw[7]);
        *(uint4*)(smem + OFF_AL(buf) + d)      = make_uint4(lw[0], lw[1], lw[2], lw[3]);
        *(uint4*)(smem + OFF_AL(buf) + d + 16) = make_uint4(lw[4], lw[5], lw[6], lw[7]);
    };

    float acc[2][8][4];
    #pragma unroll
    for (int i = 0; i < 2; i++)
        #pragma unroll
        for (int j = 0; j < 8; j++)
            #pragma unroll
            for (int q = 0; q < 4; q++) acc[i][j][q] = 0.f;

    float4 fr[4];
    cpB(0, 0); asm volatile("cp.async.commit_group;" ::: "memory");
    cpB(1, 1); asm volatile("cp.async.commit_group;" ::: "memory");
    ldA(0, fr); stA(fr, 0);
    ldA(1, fr);
    asm volatile("cp.async.wait_group 1;" ::: "memory");
    __syncthreads();

    #pragma unroll 1
    for (int t = 0; t < 16; t++) {
        const int buf = t & 1;
        const uint32_t ahb = sb + OFF_AH(buf), alb = sb + OFF_AL(buf);
        const uint32_t bb  = sb + OFF_B(buf);
        #pragma unroll
        for (int ks = 0; ks < 2; ks++) {
            const uint32_t kb = ks * 32;
            uint32_t Ah[2][4], Al[2][4], Bv[4][4];
            #pragma unroll
            for (int mt = 0; mt < 2; mt++) {
                uint32_t ro = (uint32_t)(warp_m * 32 + mt * 16 + (lane & 15)) * 80 + kb + ((lane >> 4) << 4);
                ldsm4(Ah[mt], ahb + ro);
                ldsm4(Al[mt], alb + ro);
            }
            #pragma unroll
            for (int p = 0; p < 4; p++) {
                uint32_t bo = (uint32_t)(warp_n * 64 + p * 16 + ((lane >> 4) << 3) + (lane & 7)) * 80
                              + kb + (((lane >> 3) & 1) << 4);
                ldsm4(Bv[p], bb + bo);
            }
            #pragma unroll
            for (int mt = 0; mt < 2; mt++)
                #pragma unroll
                for (int p = 0; p < 4; p++) {
                    mma_f16(acc[mt][2 * p],     Ah[mt], &Bv[p][0]);
                    mma_f16(acc[mt][2 * p + 1], Ah[mt], &Bv[p][2]);
                    mma_f16(acc[mt][2 * p],     Al[mt], &Bv[p][0]);
                    mma_f16(acc[mt][2 * p + 1], Al[mt], &Bv[p][2]);
                }
        }
        if (t == 15) break;
        __syncthreads();
        stA(fr, (t + 1) & 1);
        if (t + 2 < 16) {
            ldA(t + 2, fr);
            cpB(t + 2, buf);
            asm volatile("cp.async.commit_group;" ::: "memory");
            asm volatile("cp.async.wait_group 1;" ::: "memory");
        } else {
            asm volatile("cp.async.wait_group 0;" ::: "memory");
        }
        __syncthreads();
    }

    // epilogue: partial logits over this u-slice
    float* red = (float*)(smem + OFF_RED);
    #pragma unroll
    for (int mt = 0; mt < 2; mt++)
        #pragma unroll
        for (int hf = 0; hf < 2; hf++) {
            float p = 0.f;
            #pragma unroll
            for (int nt = 0; nt < 8; nt++) {
                int u = warp_n * 64 + nt * 8 + (lane & 3) * 2;
                p += tanh_fast(acc[mt][nt][hf * 2 + 0] + gs[u])     * vsm[u];
                p += tanh_fast(acc[mt][nt][hf * 2 + 1] + gs[u + 1]) * vsm[u + 1];
            }
            int ml = warp_m * 32 + mt * 16 + hf * 8 + (lane >> 2);
            red[ml * 9 + warp_n * 4 + (lane & 3)] = p;
        }
    __syncthreads();
    if (tid < 128) {
        float s = 0.f;
        #pragma unroll
        for (int i = 0; i < 8; i++) s += red[tid * 9 + i];
        g_lpart[us][m0 + tid] = s;
    }
}

// ---------------------------------------------------------------------------
// k_softmax: sum u-slice partials, softmax over T
// ---------------------------------------------------------------------------
__global__ __launch_bounds__(256) void k_softmax(float* __restrict__ out_w)
{
    int b = blockIdx.x, tid = threadIdx.x;
    __shared__ float smax[8], ssum[8];
    float v[8];
    float mx = -1e30f;
    #pragma unroll
    for (int i = 0; i < 8; i++) {
        int idx = b * TT + tid + i * 256;
        v[i] = g_lpart[0][idx] + g_lpart[1][idx] + g_lpart[2][idx] + g_lpart[3][idx];
        mx = fmaxf(mx, v[i]);
    }
    #pragma unroll
    for (int o = 16; o > 0; o >>= 1) mx = fmaxf(mx, __shfl_xor_sync(~0u, mx, o));
    if ((tid & 31) == 0) smax[tid >> 5] = mx;
    __syncthreads();
    mx = smax[0];
    #pragma unroll
    for (int i = 1; i < 8; i++) mx = fmaxf(mx, smax[i]);
    float s = 0.f;
    #pragma unroll
    for (int i = 0; i < 8; i++) { v[i] = expf(v[i] - mx); s += v[i]; }
    #pragma unroll
    for (int o = 16; o > 0; o >>= 1) s += __shfl_xor_sync(~0u, s, o);
    if ((tid & 31) == 0) ssum[tid >> 5] = s;
    __syncthreads();
    s = ssum[0];
    #pragma unroll
    for (int i = 1; i < 8; i++) s += ssum[i];
    float inv = 1.f / s;
    #pragma unroll
    for (int i = 0; i < 8; i++) out_w[b * TT + tid + i * 256] = v[i] * inv;
}

// ---------------------------------------------------------------------------
// k_ctx_part / k_ctx_red: context = sum_t w * F, two-stage deterministic
// ---------------------------------------------------------------------------
__global__ __launch_bounds__(256) void k_ctx_part(
    const float* __restrict__ F, const float* __restrict__ w)
{
    int tc = blockIdx.x, b = blockIdx.y, tid = threadIdx.x;
    __shared__ float ws[64];
    if (tid < 64) ws[tid] = w[b * TT + tc * 64 + tid];
    __syncthreads();
    int q = tid & 127, r2 = tid >> 7;
    const float4* F4 = (const float4*)(F + ((size_t)b * TT + (size_t)tc * 64) * DD) + q;
    float ax = 0.f, ay = 0.f, az = 0.f, aw = 0.f;
    #pragma unroll 8
    for (int i = 0; i < 32; i++) {
        int t = r2 + 2 * i;
        float wv = ws[t];
        float4 v = F4[(size_t)t * 128];
        ax = fmaf(wv, v.x, ax); ay = fmaf(wv, v.y, ay);
        az = fmaf(wv, v.z, az); aw = fmaf(wv, v.w, aw);
    }
    float4 o; o.x = ax; o.y = ay; o.z = az; o.w = aw;
    ((float4*)&g_part[b][tc][r2][0])[q] = o;
}

__global__ __launch_bounds__(512) void k_ctx_red(float* __restrict__ out_c)
{
    int b = blockIdx.x, d = threadIdx.x;
    float s = 0.f;
    const float* p = &g_part[b][0][0][0];
    #pragma unroll
    for (int i = 0; i < 64; i++) s += p[i * DD + d];
    out_c[b * DD + d] = s;
}

// ---------------------------------------------------------------------------
extern "C" void kernel_launch(void* const* d_in, const int* in_sizes, int n_in,
                              void* d_out, int out_size)
{
    const float* features = (const float*)d_in[0];
    const float* hidden   = (const float*)d_in[1];
    const float* W1_w     = (const float*)d_in[2];
    const float* W1_b     = (const float*)d_in[3];
    const float* W2_w     = (const float*)d_in[4];
    const float* W2_b     = (const float*)d_in[5];
    const float* V_w      = (const float*)d_in[6];
    // V_b cancels in softmax

    float* out   = (float*)d_out;
    float* out_c = out;               // [B, D]
    float* out_w = out + BB * DD;     // [B, T, 1]

    cudaFuncSetAttribute(k_logits, cudaFuncAttributeMaxDynamicSharedMemorySize, SMEM_BYTES);

    k_prepw  <<<512, 512>>>(W1_w);
    k_hproj  <<<BB, 512>>>(hidden, W2_w, W2_b, W1_b);
    k_logits <<<dim3(1024, 4), 256, SMEM_BYTES>>>(features, V_w);
    k_softmax<<<BB, 256>>>(out_w);
    k_ctx_part<<<dim3(32, BB), 256>>>(features, out_w);
    k_ctx_red<<<BB, 512>>>(out_c);
}

// round 7
// speedup vs baseline: 4.2070x; 1.3756x over previous
#include <cuda_runtime.h>
#include <cuda_fp16.h>
#include <cuda_bf16.h>
#include <cstdint>

#define BB 64
#define TT 2048
#define DD 512
#define UU 512

// ---------------- device scratch (no cudaMalloc allowed) ----------------
__device__ float g_hb[BB * UU];                 // h_proj + W1_b
__device__ float g_lpart[4][BB * TT];           // logits partials per u-slice
__device__ float g_part[BB][32][2][DD];         // context partials
__device__ __half g_W1f[UU * DD];               // W1^T fp16  [u][k]

// ---------------- helpers ----------------
__device__ __forceinline__ uint32_t smem_u32(const void* p) {
    uint32_t a;
    asm("{ .reg .u64 t; cvta.to.shared.u64 t, %1; cvt.u32.u64 %0, t; }" : "=r"(a) : "l"(p));
    return a;
}
__device__ __forceinline__ float tanh_fast(float x) {
    float y; asm("tanh.approx.f32 %0, %1;" : "=f"(y) : "f"(x)); return y;
}
__device__ __forceinline__ void cp16(uint32_t dst, const void* src) {
    asm volatile("cp.async.cg.shared.global [%0], [%1], 16;" :: "r"(dst), "l"(src) : "memory");
}
__device__ __forceinline__ void ldsm4(uint32_t* r, uint32_t addr) {
    asm volatile("ldmatrix.sync.aligned.m8n8.x4.shared.b16 {%0,%1,%2,%3}, [%4];"
                 : "=r"(r[0]), "=r"(r[1]), "=r"(r[2]), "=r"(r[3]) : "r"(addr));
}
__device__ __forceinline__ void mma_f16(float* c, const uint32_t* a, const uint32_t* b) {
    asm volatile("mma.sync.aligned.m16n8k16.row.col.f32.f16.f16.f32 "
                 "{%0,%1,%2,%3}, {%4,%5,%6,%7}, {%8,%9}, {%0,%1,%2,%3};"
                 : "+f"(c[0]), "+f"(c[1]), "+f"(c[2]), "+f"(c[3])
                 : "r"(a[0]), "r"(a[1]), "r"(a[2]), "r"(a[3]), "r"(b[0]), "r"(b[1]));
}

// ---------------------------------------------------------------------------
// k_prepw: W1 [k][u] -> W1^T fp16 [u][k]
// ---------------------------------------------------------------------------
__global__ __launch_bounds__(512) void k_prepw(const float* __restrict__ W1) {
    int u = blockIdx.x, k = threadIdx.x;
    g_W1f[(size_t)u * DD + k] = __float2half_rn(W1[(size_t)k * UU + u]);
}

// ---------------------------------------------------------------------------
// k_hproj: g_hb[b,u] = hidden[b,:] @ W2[:,u] + W2_b[u] + W1_b[u]
// ---------------------------------------------------------------------------
__global__ __launch_bounds__(512) void k_hproj(
    const float* __restrict__ hidden, const float* __restrict__ W2,
    const float* __restrict__ W2b, const float* __restrict__ W1b)
{
    int b = blockIdx.x, u = threadIdx.x;
    __shared__ float h[DD];
    h[u] = hidden[b * DD + u];
    __syncthreads();
    float a0 = 0.f, a1 = 0.f, a2 = 0.f, a3 = 0.f;
    #pragma unroll 4
    for (int k = 0; k < DD; k += 4) {
        a0 = fmaf(h[k + 0], W2[(k + 0) * UU + u], a0);
        a1 = fmaf(h[k + 1], W2[(k + 1) * UU + u], a1);
        a2 = fmaf(h[k + 2], W2[(k + 2) * UU + u], a2);
        a3 = fmaf(h[k + 3], W2[(k + 3) * UU + u], a3);
    }
    g_hb[b * UU + u] = ((a0 + a1) + (a2 + a3)) + W2b[u] + W1b[u];
}

// ---------------------------------------------------------------------------
// k_logits: mma.sync fp16 single-pass GEMM + fused tanh/v epilogue
//   A = features fp16, B = W1 fp16; error ~2.4e-4 rel (under 1e-3).
//   grid = (4 u-slices fastest, 1024 m-tiles) -> A tiles L2-shared by siblings
// ---------------------------------------------------------------------------
#define OFF_A(b)  ((b) * 20480 + 0)
#define OFF_B(b)  ((b) * 20480 + 10240)
#define OFF_GS 40960
#define OFF_VS 41472
#define OFF_RED 41984
#define SMEM_BYTES 46592

__global__ __launch_bounds__(256, 2)
void k_logits(const float* __restrict__ F, const float* __restrict__ V)
{
    extern __shared__ __align__(128) uint8_t smem[];
    const uint32_t sb = smem_u32(smem);
    const int tid = threadIdx.x;
    const int lane = tid & 31, wid = tid >> 5;
    const int warp_m = wid & 3, warp_n = wid >> 2;
    const int us = blockIdx.x;              // u-slice fastest -> L2 sharing of A
    const int m0 = blockIdx.y * 128;
    const int b  = m0 >> 11;

    float* gs  = (float*)(smem + OFF_GS);
    float* vsm = (float*)(smem + OFF_VS);
    if (tid < 128) {
        gs[tid]  = g_hb[b * UU + us * 128 + tid];
        vsm[tid] = V[us * 128 + tid];
    }

    const int arow = tid >> 1, ah = tid & 1;

    auto cpB = [&](int kt, int buf) {
        const __half* s = g_W1f + (size_t)(us * 128 + arow) * DD + kt * 32 + ah * 16;
        uint32_t d = (uint32_t)(arow * 80 + ah * 32);
        cp16(sb + OFF_B(buf) + d,      s);
        cp16(sb + OFF_B(buf) + d + 16, s + 8);
    };
    auto ldA = [&](int kt, float4* fr) {
        const float4* p = (const float4*)(F + (size_t)(m0 + arow) * DD + kt * 32 + ah * 16);
        fr[0] = p[0]; fr[1] = p[1]; fr[2] = p[2]; fr[3] = p[3];
    };
    auto stA = [&](const float4* fr, int buf) {
        float x[16] = {fr[0].x, fr[0].y, fr[0].z, fr[0].w, fr[1].x, fr[1].y, fr[1].z, fr[1].w,
                       fr[2].x, fr[2].y, fr[2].z, fr[2].w, fr[3].x, fr[3].y, fr[3].z, fr[3].w};
        uint32_t hw[8];
        #pragma unroll
        for (int i = 0; i < 8; i++) {
            __half hA = __float2half_rn(x[2 * i]), hC = __float2half_rn(x[2 * i + 1]);
            hw[i] = (uint32_t)__half_as_ushort(hA) | ((uint32_t)__half_as_ushort(hC) << 16);
        }
        uint32_t d = (uint32_t)(arow * 80 + ah * 32);
        *(uint4*)(smem + OFF_A(buf) + d)      = make_uint4(hw[0], hw[1], hw[2], hw[3]);
        *(uint4*)(smem + OFF_A(buf) + d + 16) = make_uint4(hw[4], hw[5], hw[6], hw[7]);
    };

    float acc[2][8][4];
    #pragma unroll
    for (int i = 0; i < 2; i++)
        #pragma unroll
        for (int j = 0; j < 8; j++)
            #pragma unroll
            for (int q = 0; q < 4; q++) acc[i][j][q] = 0.f;

    float4 fr[4];
    cpB(0, 0); asm volatile("cp.async.commit_group;" ::: "memory");
    cpB(1, 1); asm volatile("cp.async.commit_group;" ::: "memory");
    ldA(0, fr); stA(fr, 0);
    ldA(1, fr);
    asm volatile("cp.async.wait_group 1;" ::: "memory");
    __syncthreads();

    #pragma unroll 1
    for (int t = 0; t < 16; t++) {
        const int buf = t & 1;
        const uint32_t ab = sb + OFF_A(buf);
        const uint32_t bb = sb + OFF_B(buf);
        #pragma unroll
        for (int ks = 0; ks < 2; ks++) {
            const uint32_t kb = ks * 32;
            uint32_t Ah[2][4], Bv[4][4];
            #pragma unroll
            for (int mt = 0; mt < 2; mt++) {
                uint32_t ro = (uint32_t)(warp_m * 32 + mt * 16 + (lane & 15)) * 80 + kb + ((lane >> 4) << 4);
                ldsm4(Ah[mt], ab + ro);
            }
            #pragma unroll
            for (int p = 0; p < 4; p++) {
                uint32_t bo = (uint32_t)(warp_n * 64 + p * 16 + ((lane >> 4) << 3) + (lane & 7)) * 80
                              + kb + (((lane >> 3) & 1) << 4);
                ldsm4(Bv[p], bb + bo);
            }
            #pragma unroll
            for (int mt = 0; mt < 2; mt++)
                #pragma unroll
                for (int p = 0; p < 4; p++) {
                    mma_f16(acc[mt][2 * p],     Ah[mt], &Bv[p][0]);
                    mma_f16(acc[mt][2 * p + 1], Ah[mt], &Bv[p][2]);
                }
        }
        if (t == 15) break;
        __syncthreads();
        stA(fr, (t + 1) & 1);
        if (t + 2 < 16) {
            ldA(t + 2, fr);
            cpB(t + 2, buf);
            asm volatile("cp.async.commit_group;" ::: "memory");
            asm volatile("cp.async.wait_group 1;" ::: "memory");
        } else {
            asm volatile("cp.async.wait_group 0;" ::: "memory");
        }
        __syncthreads();
    }

    // epilogue: partial logits over this u-slice
    float* red = (float*)(smem + OFF_RED);
    #pragma unroll
    for (int mt = 0; mt < 2; mt++)
        #pragma unroll
        for (int hf = 0; hf < 2; hf++) {
            float p = 0.f;
            #pragma unroll
            for (int nt = 0; nt < 8; nt++) {
                int u = warp_n * 64 + nt * 8 + (lane & 3) * 2;
                p += tanh_fast(acc[mt][nt][hf * 2 + 0] + gs[u])     * vsm[u];
                p += tanh_fast(acc[mt][nt][hf * 2 + 1] + gs[u + 1]) * vsm[u + 1];
            }
            int ml = warp_m * 32 + mt * 16 + hf * 8 + (lane >> 2);
            red[ml * 9 + warp_n * 4 + (lane & 3)] = p;
        }
    __syncthreads();
    if (tid < 128) {
        float s = 0.f;
        #pragma unroll
        for (int i = 0; i < 8; i++) s += red[tid * 9 + i];
        g_lpart[us][m0 + tid] = s;
    }
}

// ---------------------------------------------------------------------------
// k_softmax: sum u-slice partials, softmax over T
// ---------------------------------------------------------------------------
__global__ __launch_bounds__(256) void k_softmax(float* __restrict__ out_w)
{
    int b = blockIdx.x, tid = threadIdx.x;
    __shared__ float smax[8], ssum[8];
    float v[8];
    float mx = -1e30f;
    #pragma unroll
    for (int i = 0; i < 8; i++) {
        int idx = b * TT + tid + i * 256;
        v[i] = g_lpart[0][idx] + g_lpart[1][idx] + g_lpart[2][idx] + g_lpart[3][idx];
        mx = fmaxf(mx, v[i]);
    }
    #pragma unroll
    for (int o = 16; o > 0; o >>= 1) mx = fmaxf(mx, __shfl_xor_sync(~0u, mx, o));
    if ((tid & 31) == 0) smax[tid >> 5] = mx;
    __syncthreads();
    mx = smax[0];
    #pragma unroll
    for (int i = 1; i < 8; i++) mx = fmaxf(mx, smax[i]);
    float s = 0.f;
    #pragma unroll
    for (int i = 0; i < 8; i++) { v[i] = expf(v[i] - mx); s += v[i]; }
    #pragma unroll
    for (int o = 16; o > 0; o >>= 1) s += __shfl_xor_sync(~0u, s, o);
    if ((tid & 31) == 0) ssum[tid >> 5] = s;
    __syncthreads();
    s = ssum[0];
    #pragma unroll
    for (int i = 1; i < 8; i++) s += ssum[i];
    float inv = 1.f / s;
    #pragma unroll
    for (int i = 0; i < 8; i++) out_w[b * TT + tid + i * 256] = v[i] * inv;
}

// ---------------------------------------------------------------------------
// k_ctx_part / k_ctx_red: context = sum_t w * F, two-stage deterministic
// ---------------------------------------------------------------------------
__global__ __launch_bounds__(256) void k_ctx_part(
    const float* __restrict__ F, const float* __restrict__ w)
{
    int tc = blockIdx.x, b = blockIdx.y, tid = threadIdx.x;
    __shared__ float ws[64];
    if (tid < 64) ws[tid] = w[b * TT + tc * 64 + tid];
    __syncthreads();
    int q = tid & 127, r2 = tid >> 7;
    const float4* F4 = (const float4*)(F + ((size_t)b * TT + (size_t)tc * 64) * DD) + q;
    float ax = 0.f, ay = 0.f, az = 0.f, aw = 0.f;
    #pragma unroll 8
    for (int i = 0; i < 32; i++) {
        int t = r2 + 2 * i;
        float wv = ws[t];
        float4 v = F4[(size_t)t * 128];
        ax = fmaf(wv, v.x, ax); ay = fmaf(wv, v.y, ay);
        az = fmaf(wv, v.z, az); aw = fmaf(wv, v.w, aw);
    }
    float4 o; o.x = ax; o.y = ay; o.z = az; o.w = aw;
    ((float4*)&g_part[b][tc][r2][0])[q] = o;
}

__global__ __launch_bounds__(512) void k_ctx_red(float* __restrict__ out_c)
{
    int b = blockIdx.x, d = threadIdx.x;
    float s = 0.f;
    const float* p = &g_part[b][0][0][0];
    #pragma unroll
    for (int i = 0; i < 64; i++) s += p[i * DD + d];
    out_c[b * DD + d] = s;
}

// ---------------------------------------------------------------------------
extern "C" void kernel_launch(void* const* d_in, const int* in_sizes, int n_in,
                              void* d_out, int out_size)
{
    const float* features = (const float*)d_in[0];
    const float* hidden   = (const float*)d_in[1];
    const float* W1_w     = (const float*)d_in[2];
    const float* W1_b     = (const float*)d_in[3];
    const float* W2_w     = (const float*)d_in[4];
    const float* W2_b     = (const float*)d_in[5];
    const float* V_w      = (const float*)d_in[6];
    // V_b cancels in softmax

    float* out   = (float*)d_out;
    float* out_c = out;               // [B, D]
    float* out_w = out + BB * DD;     // [B, T, 1]

    cudaFuncSetAttribute(k_logits, cudaFuncAttributeMaxDynamicSharedMemorySize, SMEM_BYTES);

    k_prepw  <<<512, 512>>>(W1_w);
    k_hproj  <<<BB, 512>>>(hidden, W2_w, W2_b, W1_b);
    k_logits <<<dim3(4, 1024), 256, SMEM_BYTES>>>(features, V_w);
    k_softmax<<<BB, 256>>>(out_w);
    k_ctx_part<<<dim3(32, BB), 256>>>(features, out_w);
    k_ctx_red<<<BB, 512>>>(out_c);
}